// round 14
// baseline (speedup 1.0000x reference)
#include <cuda_runtime.h>
#include <cuda_bf16.h>
#include <cstdint>

// ---------------- problem constants ----------------
#define MROWS 8192          // B*D = 256*32
#define KDIM  1024
#define NCOLS 1024
#define NSTEPS 6

// ---------------- scratch (__device__ globals; no allocation) ----------------
__device__ __nv_bfloat16 g_ah[2][MROWS * KDIM];      // activation hi, ping/pong
__device__ __nv_bfloat16 g_al[2][MROWS * KDIM];      // activation lo
__device__ __nv_bfloat16 g_wh[NSTEPS][KDIM * NCOLS]; // Wt hi: [n][k]
__device__ __nv_bfloat16 g_wl[NSTEPS][KDIM * NCOLS]; // Wt lo

// ---------------- GEMM tiling: 64 x 128, BK=32, 2 stages, 3 CTAs/SM ----------------
#define BM 64
#define BN 128
#define BK 32
#define NKT (KDIM / BK)       // 32
#define NTHREADS 256

#define ROW_B   48
#define ABLK_B  (64 * ROW_B)            // 3072
#define AREG_B  (4 * ABLK_B)            // 12288
#define BBLK_B  (128 * ROW_B)           // 6144
#define BREG_B  (4 * BBLK_B)            // 24576
#define STAGE_B (AREG_B + BREG_B)       // 36864
#define SMEM_BYTES (2 * STAGE_B)        // 73728 -> 3 CTAs/SM (221 KB of 227)

__device__ __forceinline__ uint32_t s2u(const void* p) {
    uint32_t a;
    asm("{ .reg .u64 t; cvta.to.shared.u64 t, %1; cvt.u32.u64 %0, t; }" : "=r"(a) : "l"(p));
    return a;
}
__device__ __forceinline__ void ldm4(uint32_t* r, uint32_t a) {
    asm volatile("ldmatrix.sync.aligned.m8n8.x4.shared.b16 {%0,%1,%2,%3}, [%4];"
                 : "=r"(r[0]), "=r"(r[1]), "=r"(r[2]), "=r"(r[3]) : "r"(a));
}
__device__ __forceinline__ void mma_bf16(float* d, const uint32_t* a, const uint32_t* b) {
    asm volatile("mma.sync.aligned.m16n8k16.row.col.f32.bf16.bf16.f32 "
                 "{%0,%1,%2,%3}, {%4,%5,%6,%7}, {%8,%9}, {%0,%1,%2,%3};"
                 : "+f"(d[0]), "+f"(d[1]), "+f"(d[2]), "+f"(d[3])
                 : "r"(a[0]), "r"(a[1]), "r"(a[2]), "r"(a[3]), "r"(b[0]), "r"(b[1]));
}
__device__ __forceinline__ void split_bf16(float v, __nv_bfloat16& h, __nv_bfloat16& l) {
    h = __float2bfloat16(v);
    l = __float2bfloat16(v - __bfloat162float(h));
}

// ---------------- prep kernels (unchanged, validated) ----------------
__global__ void prep_x(const float* __restrict__ X) {
    __shared__ float t[32][33];
    const int b = blockIdx.x >> 5, j = blockIdx.x & 31;
    const int x = threadIdx.x, y = threadIdx.y;
    t[y][x] = X[b * 32768 + y * 1024 + j * 32 + x];   // y=i, x=f
    __syncthreads();
    const float v = t[x][y];
    __nv_bfloat16 h, l;
    split_bf16(v, h, l);
    const int addr = (b * 32 + y) * 1024 + j * 32 + x;
    g_ah[0][addr] = h;
    g_al[0][addr] = l;
}
__global__ void prep_w(const float* __restrict__ W) {
    __shared__ float t[32][33];
    const int s = blockIdx.z;
    const int k0 = blockIdx.x * 32, n0 = blockIdx.y * 32;
    const int x = threadIdx.x, y = threadIdx.y;
    const int kp = k0 + y;
    const int wrow = (kp & 31) * 32 + (kp >> 5);
    t[y][x] = W[s * 1048576 + wrow * 1024 + n0 + x];
    __syncthreads();
    const float v = t[x][y];
    __nv_bfloat16 h, l;
    split_bf16(v, h, l);
    const int addr = (n0 + y) * 1024 + k0 + x;
    g_wh[s][addr] = h;
    g_wl[s][addr] = l;
}

// ---------------- bf16x3 mma GEMM: 8 warps (2m x 4n), warp tile 32x32 ----------------
template <bool EPI>
__global__ __launch_bounds__(NTHREADS, 3)
void entangler_mma(int src, int dst, int s,
                   const float* __restrict__ bias, float* __restrict__ out) {
    extern __shared__ char smem[];
    const uint32_t smem_u = s2u(smem);

    const int tid  = threadIdx.x;
    const int wid  = tid >> 5;
    const int lane = tid & 31;
    const int col0 = blockIdx.x * BN;
    const int row0 = blockIdx.y * BM;
    const int warp_m = (wid & 1) * 32;
    const int warp_n = (wid >> 1) * 32;

    const __nv_bfloat16* __restrict__ Ahi = g_ah[src];
    const __nv_bfloat16* __restrict__ Alo = g_al[src];
    const __nv_bfloat16* __restrict__ Whi = g_wh[s];
    const __nv_bfloat16* __restrict__ Wlo = g_wl[s];
    __nv_bfloat16* __restrict__ Ahd = g_ah[dst];
    __nv_bfloat16* __restrict__ Ald = g_al[dst];

    float acc[2][4][4];
#pragma unroll
    for (int mt = 0; mt < 2; mt++)
#pragma unroll
        for (int nt = 0; nt < 4; nt++)
#pragma unroll
            for (int q = 0; q < 4; q++) acc[mt][nt][q] = 0.0f;

    // ---- cp.async staging: A 512 chunks (2/thr), B 1024 chunks (4/thr) ----
    auto issue = [&](int kt, int stg) {
        const uint32_t sbase = smem_u + stg * STAGE_B;
#pragma unroll
        for (int t = 0; t < 2; t++) {
            const int idx  = tid + t * NTHREADS;     // 0..511
            const int m_l  = idx >> 3;               // 0..63
            const int sub  = idx & 7;
            const int hl   = sub >> 2;
            const int ch   = sub & 3;
            const int ks   = ch >> 1;
            const int half = ch & 1;
            const uint32_t soff = ((hl * 2 + ks) * 64 + m_l) * ROW_B + half * 16;
            const __nv_bfloat16* ga =
                (hl ? Alo : Ahi) + (row0 + m_l) * 1024 + kt * 32 + ch * 8;
            asm volatile("cp.async.cg.shared.global [%0], [%1], 16;"
                         :: "r"(sbase + soff), "l"(ga));
        }
#pragma unroll
        for (int t = 0; t < 4; t++) {
            const int idx  = tid + t * NTHREADS;     // 0..1023
            const int n_l  = idx >> 3;               // 0..127
            const int sub  = idx & 7;
            const int hl   = sub >> 2;
            const int ch   = sub & 3;
            const int ks   = ch >> 1;
            const int half = ch & 1;
            const uint32_t soff = AREG_B + ((hl * 2 + ks) * 128 + n_l) * ROW_B + half * 16;
            const __nv_bfloat16* gb =
                (hl ? Wlo : Whi) + (col0 + n_l) * 1024 + kt * 32 + ch * 8;
            asm volatile("cp.async.cg.shared.global [%0], [%1], 16;"
                         :: "r"(sbase + soff), "l"(gb));
        }
        asm volatile("cp.async.commit_group;" ::: "memory");
    };

    // ---- ldmatrix lane mappings (validated round 6) ----
    const int a_lr = (lane & 7) + ((lane >> 3) & 1) * 8;
    const int a_lb = (lane >> 4) * 16;
    const int b_nr = (lane >> 4) * 8 + (lane & 7);
    const int b_lb = ((lane >> 3) & 1) * 16;

    auto compute = [&](int stg) {
        const uint32_t sbase = smem_u + stg * STAGE_B;
#pragma unroll
        for (int ks = 0; ks < 2; ks++) {
            uint32_t ah[2][4], al[2][4];
#pragma unroll
            for (int mt = 0; mt < 2; mt++) {
                const uint32_t ra = (warp_m + mt * 16 + a_lr) * ROW_B + a_lb;
                ldm4(ah[mt], sbase + (0 + ks) * ABLK_B + ra);
                ldm4(al[mt], sbase + (2 + ks) * ABLK_B + ra);
            }
#pragma unroll
            for (int ntp = 0; ntp < 2; ntp++) {
                const uint32_t rb = (warp_n + ntp * 16 + b_nr) * ROW_B + b_lb;
                uint32_t bh[4], bl[4];
                ldm4(bh, sbase + AREG_B + (0 + ks) * BBLK_B + rb);
                ldm4(bl, sbase + AREG_B + (2 + ks) * BBLK_B + rb);
                const int n0 = 2 * ntp;
                // 12 MMAs, 3 passes: same-acc dep distance 4
#pragma unroll
                for (int mt = 0; mt < 2; mt++) {
                    mma_bf16(acc[mt][n0],     ah[mt], bh);
                    mma_bf16(acc[mt][n0 + 1], ah[mt], bh + 2);
                }
#pragma unroll
                for (int mt = 0; mt < 2; mt++) {
                    mma_bf16(acc[mt][n0],     ah[mt], bl);
                    mma_bf16(acc[mt][n0 + 1], ah[mt], bl + 2);
                }
#pragma unroll
                for (int mt = 0; mt < 2; mt++) {
                    mma_bf16(acc[mt][n0],     al[mt], bh);
                    mma_bf16(acc[mt][n0 + 1], al[mt], bh + 2);
                }
            }
        }
    };

    // ---- 2-stage pipeline ----
    issue(0, 0);
#pragma unroll 1
    for (int kt = 0; kt < NKT; kt++) {
        if (kt + 1 < NKT) {
            issue(kt + 1, (kt + 1) & 1);
            asm volatile("cp.async.wait_group 1;" ::: "memory");
        } else {
            asm volatile("cp.async.wait_group 0;" ::: "memory");
        }
        __syncthreads();
        compute(kt & 1);
        if (kt + 1 < NKT) __syncthreads();
    }

    // ---- epilogue ----
    const int lrow = lane >> 2;
    const int lcol = (lane & 3) * 2;
#pragma unroll
    for (int mt = 0; mt < 2; mt++) {
#pragma unroll
        for (int nt = 0; nt < 4; nt++) {
            const int gr0 = row0 + warp_m + mt * 16 + lrow;
            const int gn  = col0 + warp_n + nt * 8 + lcol;
#pragma unroll
            for (int half = 0; half < 2; half++) {
                const int r = gr0 + half * 8;
                float v0 = acc[mt][nt][half * 2 + 0];
                float v1 = acc[mt][nt][half * 2 + 1];
                if (EPI) {
                    const int f = r & 31;
                    v0 = fmaxf(v0 + bias[f * 1024 + gn], 0.0f);
                    v1 = fmaxf(v1 + bias[f * 1024 + gn + 1], 0.0f);
                    *(float2*)(out + r * 1024 + gn) = make_float2(v0, v1);
                } else {
                    // scatter into next step's row-major A layout
                    const int b = r >> 5, f = r & 31;
                    const int addr = (b * 32 + (gn >> 5)) * 1024 + f * 32 + (gn & 31);
                    __nv_bfloat16 h0, l0, h1, l1;
                    split_bf16(v0, h0, l0);
                    split_bf16(v1, h1, l1);
                    __nv_bfloat162 hp; hp.x = h0; hp.y = h1;
                    __nv_bfloat162 lp; lp.x = l0; lp.y = l1;
                    *(__nv_bfloat162*)(&Ahd[addr]) = hp;
                    *(__nv_bfloat162*)(&Ald[addr]) = lp;
                }
            }
        }
    }
}

// ---------------- launch ----------------
extern "C" void kernel_launch(void* const* d_in, const int* in_sizes, int n_in,
                              void* d_out, int out_size) {
    const float* X     = (const float*)d_in[0];
    const float* nodes = (const float*)d_in[1];
    const float* bias  = (const float*)d_in[2];
    float* out = (float*)d_out;

    cudaFuncSetAttribute(entangler_mma<false>,
                         cudaFuncAttributeMaxDynamicSharedMemorySize, SMEM_BYTES);
    cudaFuncSetAttribute(entangler_mma<true>,
                         cudaFuncAttributeMaxDynamicSharedMemorySize, SMEM_BYTES);

    prep_x<<<MROWS, dim3(32, 32)>>>(X);
    prep_w<<<dim3(32, 32, NSTEPS), dim3(32, 32)>>>(nodes);

    dim3 grid(NCOLS / BN, MROWS / BM);   // (8, 128) = 1024 CTAs
    entangler_mma<false><<<grid, NTHREADS, SMEM_BYTES>>>(0, 1, 0, bias, nullptr);
    entangler_mma<false><<<grid, NTHREADS, SMEM_BYTES>>>(1, 0, 1, bias, nullptr);
    entangler_mma<false><<<grid, NTHREADS, SMEM_BYTES>>>(0, 1, 2, bias, nullptr);
    entangler_mma<false><<<grid, NTHREADS, SMEM_BYTES>>>(1, 0, 3, bias, nullptr);
    entangler_mma<false><<<grid, NTHREADS, SMEM_BYTES>>>(0, 1, 4, bias, nullptr);
    entangler_mma<true ><<<grid, NTHREADS, SMEM_BYTES>>>(1, 0, 5, bias, out);
}

// round 16
// speedup vs baseline: 2.6933x; 2.6933x over previous
#include <cuda_runtime.h>
#include <cuda_bf16.h>
#include <cstdint>

// ---------------- problem constants ----------------
#define MROWS 8192          // B*D = 256*32
#define KDIM  1024
#define NCOLS 1024
#define NSTEPS 6

// ---------------- scratch (__device__ globals; no allocation) ----------------
__device__ float g_a[2][MROWS * KDIM];          // activations (tf32-in-fp32), ping/pong
__device__ float g_w[NSTEPS][KDIM * NCOLS];     // Wt: [n][k], tf32-rounded

// ---------------- GEMM tiling: 128x128, BK=32 (4 x k8), 3 stages, 2 CTAs/SM ----------------
#define BM 128
#define BN 128
#define BK 32
#define NKT (KDIM / BK)       // 32
#define NSTAGE 3
#define NTHREADS 256

// smem row: 32 tf32 = 128B data + 16B pad = 144B (ldmatrix: rows hit banks 4r..4r+3)
#define ROW_B   144
#define TILE_B  (128 * ROW_B)           // 18432
#define STAGE_B (2 * TILE_B)            // 36864 (A then B)
#define SMEM_BYTES (NSTAGE * STAGE_B)   // 110592 -> 2 CTAs/SM

__device__ __forceinline__ uint32_t s2u(const void* p) {
    uint32_t a;
    asm("{ .reg .u64 t; cvta.to.shared.u64 t, %1; cvt.u32.u64 %0, t; }" : "=r"(a) : "l"(p));
    return a;
}
__device__ __forceinline__ void ldm4(uint32_t* r, uint32_t a) {
    asm volatile("ldmatrix.sync.aligned.m8n8.x4.shared.b16 {%0,%1,%2,%3}, [%4];"
                 : "=r"(r[0]), "=r"(r[1]), "=r"(r[2]), "=r"(r[3]) : "r"(a));
}
// m16n8k8 tf32: D += A x B  (A: 4 regs, B: 2 regs, fp32 acc)
__device__ __forceinline__ void mma_tf32(float* d, const uint32_t* a, const uint32_t* b) {
    asm volatile("mma.sync.aligned.m16n8k8.row.col.f32.tf32.tf32.f32 "
                 "{%0,%1,%2,%3}, {%4,%5,%6,%7}, {%8,%9}, {%0,%1,%2,%3};"
                 : "+f"(d[0]), "+f"(d[1]), "+f"(d[2]), "+f"(d[3])
                 : "r"(a[0]), "r"(a[1]), "r"(a[2]), "r"(a[3]), "r"(b[0]), "r"(b[1]));
}
__device__ __forceinline__ float to_tf32(float v) {
    float o;
    asm("cvt.rna.tf32.f32 %0, %1;" : "=f"(o) : "f"(v));
    return o;
}

// ---------------- prep kernels ----------------
// A0[(b,f)][k=j*32+i] = tf32(X[b,i,j,f])
__global__ void prep_x(const float* __restrict__ X) {
    __shared__ float t[32][33];
    const int b = blockIdx.x >> 5, j = blockIdx.x & 31;
    const int x = threadIdx.x, y = threadIdx.y;
    t[y][x] = X[b * 32768 + y * 1024 + j * 32 + x];   // y=i, x=f (coalesced)
    __syncthreads();
    g_a[0][(b * 32 + y) * 1024 + j * 32 + x] = to_tf32(t[x][y]);
}
// Wt[s][n][k] = tf32(W[s][(k&31)*32 + (k>>5)][n])
__global__ void prep_w(const float* __restrict__ W) {
    __shared__ float t[32][33];
    const int s = blockIdx.z;
    const int k0 = blockIdx.x * 32, n0 = blockIdx.y * 32;
    const int x = threadIdx.x, y = threadIdx.y;
    const int kp = k0 + y;
    const int wrow = (kp & 31) * 32 + (kp >> 5);
    t[y][x] = W[s * 1048576 + wrow * 1024 + n0 + x];
    __syncthreads();
    g_w[s][(n0 + y) * 1024 + k0 + x] = to_tf32(t[x][y]);
}

// ---------------- tf32 mma GEMM: 8 warps (4m x 2n), warp tile 32x64 ----------------
template <bool EPI>
__global__ __launch_bounds__(NTHREADS, 2)
void entangler_mma(int src, int dst, int s,
                   const float* __restrict__ bias, float* __restrict__ out) {
    extern __shared__ char smem[];
    const uint32_t smem_u = s2u(smem);

    const int tid  = threadIdx.x;
    const int wid  = tid >> 5;
    const int lane = tid & 31;
    const int col0 = blockIdx.x * BN;
    const int row0 = blockIdx.y * BM;
    const int warp_m = (wid & 3) * 32;
    const int warp_n = (wid >> 2) * 64;

    const float* __restrict__ A = g_a[src];
    const float* __restrict__ W = g_w[s];
    float* __restrict__ Ad = g_a[dst];

    float acc[2][8][4];
#pragma unroll
    for (int mt = 0; mt < 2; mt++)
#pragma unroll
        for (int nt = 0; nt < 8; nt++)
#pragma unroll
            for (int q = 0; q < 4; q++) acc[mt][nt][q] = 0.0f;

    // ---- cp.async staging: A 1024 + B 1024 16B-chunks, 8 per thread ----
    auto issue = [&](int kt, int stg) {
        const uint32_t sbase = smem_u + stg * STAGE_B;
#pragma unroll
        for (int t = 0; t < 4; t++) {
            const int idx = tid + t * NTHREADS;      // 0..1023
            const int m_l = idx >> 3;                // 0..127
            const int ch  = idx & 7;                 // 16B chunk (4 floats)
            const uint32_t soff = m_l * ROW_B + ch * 16;
            const float* ga = A + (row0 + m_l) * 1024 + kt * 32 + ch * 4;
            asm volatile("cp.async.cg.shared.global [%0], [%1], 16;"
                         :: "r"(sbase + soff), "l"(ga));
            const float* gb = W + (col0 + m_l) * 1024 + kt * 32 + ch * 4;
            asm volatile("cp.async.cg.shared.global [%0], [%1], 16;"
                         :: "r"(sbase + TILE_B + soff), "l"(gb));
        }
        asm volatile("cp.async.commit_group;" ::: "memory");
    };

    // ---- ldmatrix lane mappings (same proven pattern; 16B half = 4 tf32 k-values) ----
    const int a_lr = (lane & 7) + ((lane >> 3) & 1) * 8;
    const int a_lb = (lane >> 4) * 16;
    const int b_nr = (lane >> 4) * 8 + (lane & 7);
    const int b_lb = ((lane >> 3) & 1) * 16;

    auto compute = [&](int stg) {
        const uint32_t sbase = smem_u + stg * STAGE_B;
#pragma unroll
        for (int ks = 0; ks < 4; ks++) {             // 4 x k8 steps
            uint32_t ah[2][4];
#pragma unroll
            for (int mt = 0; mt < 2; mt++) {
                const uint32_t ra = (warp_m + mt * 16 + a_lr) * ROW_B + ks * 32 + a_lb;
                ldm4(ah[mt], sbase + ra);            // a0..a3 frag for m16, k8
            }
#pragma unroll
            for (int ntp = 0; ntp < 4; ntp++) {
                const uint32_t rb = (warp_n + ntp * 16 + b_nr) * ROW_B + ks * 32 + b_lb;
                uint32_t bb[4];                      // {n0-7:b0,b1, n8-15:b0,b1}
                ldm4(bb, sbase + TILE_B + rb);
                const int n0 = 2 * ntp;
#pragma unroll
                for (int mt = 0; mt < 2; mt++) {
                    mma_tf32(acc[mt][n0],     ah[mt], bb);
                    mma_tf32(acc[mt][n0 + 1], ah[mt], bb + 2);
                }
            }
        }
    };

    // ---- 3-stage pipeline, single sync per iteration ----
    issue(0, 0);
    issue(1, 1);
#pragma unroll 1
    for (int kt = 0; kt < NKT; kt++) {
        if (kt + 1 < NKT)
            asm volatile("cp.async.wait_group 1;" ::: "memory");
        else
            asm volatile("cp.async.wait_group 0;" ::: "memory");
        __syncthreads();
        if (kt + 2 < NKT) issue(kt + 2, (kt + 2) % NSTAGE);
        compute(kt % NSTAGE);
    }

    // ---- epilogue ----
    const int lrow = lane >> 2;
    const int lcol = (lane & 3) * 2;
#pragma unroll
    for (int mt = 0; mt < 2; mt++) {
#pragma unroll
        for (int nt = 0; nt < 8; nt++) {
            const int gr0 = row0 + warp_m + mt * 16 + lrow;
            const int gn  = col0 + warp_n + nt * 8 + lcol;
#pragma unroll
            for (int half = 0; half < 2; half++) {
                const int r = gr0 + half * 8;
                float v0 = acc[mt][nt][half * 2 + 0];
                float v1 = acc[mt][nt][half * 2 + 1];
                if (EPI) {
                    const int f = r & 31;
                    v0 = fmaxf(v0 + bias[f * 1024 + gn], 0.0f);
                    v1 = fmaxf(v1 + bias[f * 1024 + gn + 1], 0.0f);
                    *(float2*)(out + r * 1024 + gn) = make_float2(v0, v1);
                } else {
                    // scatter into next step's row-major A layout, tf32-rounded
                    const int b = r >> 5, f = r & 31;
                    const int addr = (b * 32 + (gn >> 5)) * 1024 + f * 32 + (gn & 31);
                    *(float2*)(&Ad[addr]) = make_float2(to_tf32(v0), to_tf32(v1));
                }
            }
        }
    }
}

// ---------------- launch ----------------
extern "C" void kernel_launch(void* const* d_in, const int* in_sizes, int n_in,
                              void* d_out, int out_size) {
    const float* X     = (const float*)d_in[0];
    const float* nodes = (const float*)d_in[1];
    const float* bias  = (const float*)d_in[2];
    float* out = (float*)d_out;

    cudaFuncSetAttribute(entangler_mma<false>,
                         cudaFuncAttributeMaxDynamicSharedMemorySize, SMEM_BYTES);
    cudaFuncSetAttribute(entangler_mma<true>,
                         cudaFuncAttributeMaxDynamicSharedMemorySize, SMEM_BYTES);

    prep_x<<<MROWS, dim3(32, 32)>>>(X);
    prep_w<<<dim3(32, 32, NSTEPS), dim3(32, 32)>>>(nodes);

    dim3 grid(NCOLS / BN, MROWS / BM);   // (8, 64) = 512 CTAs
    entangler_mma<false><<<grid, NTHREADS, SMEM_BYTES>>>(0, 1, 0, bias, nullptr);
    entangler_mma<false><<<grid, NTHREADS, SMEM_BYTES>>>(1, 0, 1, bias, nullptr);
    entangler_mma<false><<<grid, NTHREADS, SMEM_BYTES>>>(0, 1, 2, bias, nullptr);
    entangler_mma<false><<<grid, NTHREADS, SMEM_BYTES>>>(1, 0, 3, bias, nullptr);
    entangler_mma<false><<<grid, NTHREADS, SMEM_BYTES>>>(0, 1, 4, bias, nullptr);
    entangler_mma<true ><<<grid, NTHREADS, SMEM_BYTES>>>(1, 0, 5, bias, out);
}

// round 17
// speedup vs baseline: 2.8620x; 1.0626x over previous
#include <cuda_runtime.h>
#include <cuda_bf16.h>
#include <cstdint>

// ---------------- problem constants ----------------
#define MROWS 8192          // B*D = 256*32
#define KDIM  1024
#define NCOLS 1024
#define NSTEPS 6

// ---------------- scratch (__device__ globals; no allocation) ----------------
__device__ float g_a[2][MROWS * KDIM];          // activations (tf32-in-fp32), ping/pong
__device__ float g_w[NSTEPS][KDIM * NCOLS];     // Wt: [n][k], tf32-rounded

// ---------------- GEMM tiling: 128x128, BK=32 (4 x k8), 2 stages, 2 CTAs/SM ----------------
#define BM 128
#define BN 128
#define BK 32
#define NKT (KDIM / BK)       // 32
#define NTHREADS 256

// smem row: 32 tf32 = 128B data + 16B pad = 144B
#define ROW_B   144
#define TILE_B  (128 * ROW_B)           // 18432
#define STAGE_B (2 * TILE_B)            // 36864 (A then B)
// layout: [0..64) mbarriers (full0, full1, free0, free1), [1024..) 2 stages
#define MB_FULL0 0
#define MB_FULL1 8
#define MB_FREE0 16
#define MB_FREE1 24
#define STAGE_OFF 1024
#define SMEM_BYTES (STAGE_OFF + 2 * STAGE_B)   // 74752 -> 2 CTAs/SM

__device__ __forceinline__ uint32_t s2u(const void* p) {
    uint32_t a;
    asm("{ .reg .u64 t; cvta.to.shared.u64 t, %1; cvt.u32.u64 %0, t; }" : "=r"(a) : "l"(p));
    return a;
}
__device__ __forceinline__ void ldm4(uint32_t* r, uint32_t a) {
    asm volatile("ldmatrix.sync.aligned.m8n8.x4.shared.b16 {%0,%1,%2,%3}, [%4];"
                 : "=r"(r[0]), "=r"(r[1]), "=r"(r[2]), "=r"(r[3]) : "r"(a));
}
__device__ __forceinline__ void mma_tf32(float* d, const uint32_t* a, const uint32_t* b) {
    asm volatile("mma.sync.aligned.m16n8k8.row.col.f32.tf32.tf32.f32 "
                 "{%0,%1,%2,%3}, {%4,%5,%6,%7}, {%8,%9}, {%0,%1,%2,%3};"
                 : "+f"(d[0]), "+f"(d[1]), "+f"(d[2]), "+f"(d[3])
                 : "r"(a[0]), "r"(a[1]), "r"(a[2]), "r"(a[3]), "r"(b[0]), "r"(b[1]));
}
__device__ __forceinline__ float to_tf32(float v) {
    float o;
    asm("cvt.rna.tf32.f32 %0, %1;" : "=f"(o) : "f"(v));
    return o;
}
// ---- mbarrier helpers (mbarrier PTX verified OK on sm_103 base in earlier rounds) ----
__device__ __forceinline__ void mb_init(uint32_t addr, uint32_t cnt) {
    asm volatile("mbarrier.init.shared.b64 [%0], %1;" :: "r"(addr), "r"(cnt) : "memory");
}
__device__ __forceinline__ void mb_arrive(uint32_t addr) {
    uint64_t st;
    asm volatile("mbarrier.arrive.shared.b64 %0, [%1];" : "=l"(st) : "r"(addr) : "memory");
}
__device__ __forceinline__ void cpasync_arrive(uint32_t addr) {
    asm volatile("cp.async.mbarrier.arrive.noinc.shared.b64 [%0];" :: "r"(addr) : "memory");
}
__device__ __forceinline__ void mb_wait(uint32_t addr, uint32_t phase) {
    asm volatile(
        "{\n\t.reg .pred P;\n\t"
        "LW_%=:\n\t"
        "mbarrier.try_wait.parity.acquire.cta.shared::cta.b64 P, [%0], %1, 0x989680;\n\t"
        "@P bra LD_%=;\n\t"
        "bra LW_%=;\n\t"
        "LD_%=:\n\t}"
        :: "r"(addr), "r"(phase) : "memory");
}

// ---------------- prep kernels ----------------
__global__ void prep_x(const float* __restrict__ X) {
    __shared__ float t[32][33];
    const int b = blockIdx.x >> 5, j = blockIdx.x & 31;
    const int x = threadIdx.x, y = threadIdx.y;
    t[y][x] = X[b * 32768 + y * 1024 + j * 32 + x];   // y=i, x=f (coalesced)
    __syncthreads();
    g_a[0][(b * 32 + y) * 1024 + j * 32 + x] = to_tf32(t[x][y]);
}
__global__ void prep_w(const float* __restrict__ W) {
    __shared__ float t[32][33];
    const int s = blockIdx.z;
    const int k0 = blockIdx.x * 32, n0 = blockIdx.y * 32;
    const int x = threadIdx.x, y = threadIdx.y;
    const int kp = k0 + y;
    const int wrow = (kp & 31) * 32 + (kp >> 5);
    t[y][x] = W[s * 1048576 + wrow * 1024 + n0 + x];
    __syncthreads();
    g_w[s][(n0 + y) * 1024 + k0 + x] = to_tf32(t[x][y]);
}

// ---------------- tf32 mma GEMM, async per-warp pipeline ----------------
template <bool EPI>
__global__ __launch_bounds__(NTHREADS, 2)
void entangler_mma(int src, int dst, int s,
                   const float* __restrict__ bias, float* __restrict__ out) {
    extern __shared__ char smem[];
    const uint32_t smem_u = s2u(smem);

    const int tid  = threadIdx.x;
    const int wid  = tid >> 5;
    const int lane = tid & 31;
    const int col0 = blockIdx.x * BN;
    const int row0 = blockIdx.y * BM;
    const int warp_m = (wid & 3) * 32;
    const int warp_n = (wid >> 2) * 64;

    const float* __restrict__ A = g_a[src];
    const float* __restrict__ W = g_w[s];
    float* __restrict__ Ad = g_a[dst];

    // mbarrier init
    if (tid == 0) {
        mb_init(smem_u + MB_FULL0, NTHREADS);
        mb_init(smem_u + MB_FULL1, NTHREADS);
        mb_init(smem_u + MB_FREE0, NTHREADS);
        mb_init(smem_u + MB_FREE1, NTHREADS);
    }
    __syncthreads();

    float acc[2][8][4];
#pragma unroll
    for (int mt = 0; mt < 2; mt++)
#pragma unroll
        for (int nt = 0; nt < 8; nt++)
#pragma unroll
            for (int q = 0; q < 4; q++) acc[mt][nt][q] = 0.0f;

    // per-thread load mapping (8 x 16B chunks: 4 A + 4 B)
    const int lm  = (tid * 4) >> 3;          // handled below via idx loop

    auto issue = [&](int kt, int stg) {
        const uint32_t sbase = smem_u + STAGE_OFF + stg * STAGE_B;
#pragma unroll
        for (int t = 0; t < 4; t++) {
            const int idx = tid + t * NTHREADS;      // 0..1023
            const int m_l = idx >> 3;                // 0..127
            const int ch  = idx & 7;                 // 16B chunk
            const uint32_t soff = m_l * ROW_B + ch * 16;
            const float* ga = A + (row0 + m_l) * 1024 + kt * 32 + ch * 4;
            asm volatile("cp.async.cg.shared.global [%0], [%1], 16;"
                         :: "r"(sbase + soff), "l"(ga));
            const float* gb = W + (col0 + m_l) * 1024 + kt * 32 + ch * 4;
            asm volatile("cp.async.cg.shared.global [%0], [%1], 16;"
                         :: "r"(sbase + TILE_B + soff), "l"(gb));
        }
    };

    const int a_lr = (lane & 7) + ((lane >> 3) & 1) * 8;
    const int a_lb = (lane >> 4) * 16;
    const int b_nr = (lane >> 4) * 8 + (lane & 7);
    const int b_lb = ((lane >> 3) & 1) * 16;

    auto compute = [&](int stg) {
        const uint32_t sbase = smem_u + STAGE_OFF + stg * STAGE_B;
#pragma unroll
        for (int ks = 0; ks < 4; ks++) {
            uint32_t ah[2][4];
#pragma unroll
            for (int mt = 0; mt < 2; mt++) {
                const uint32_t ra = (warp_m + mt * 16 + a_lr) * ROW_B + ks * 32 + a_lb;
                ldm4(ah[mt], sbase + ra);
            }
#pragma unroll
            for (int ntp = 0; ntp < 4; ntp++) {
                const uint32_t rb = (warp_n + ntp * 16 + b_nr) * ROW_B + ks * 32 + b_lb;
                uint32_t bb[4];
                ldm4(bb, sbase + TILE_B + rb);
                const int n0 = 2 * ntp;
#pragma unroll
                for (int mt = 0; mt < 2; mt++) {
                    mma_tf32(acc[mt][n0],     ah[mt], bb);
                    mma_tf32(acc[mt][n0 + 1], ah[mt], bb + 2);
                }
            }
        }
    };

    // ---- async pipeline: 2 stages, per-warp progress via mbarriers ----
    // tile t lives in stage t&1.
    issue(0, 0);
    cpasync_arrive(smem_u + MB_FULL0);

    int pf0 = 0, pf1 = 0, pe0 = 0, pe1 = 0;

#pragma unroll 1
    for (int kt = 0; kt < NKT; kt += 2) {
        // ---- sub-iter s=0 (tile kt) ----
        {
            if (kt + 1 < NKT) {                       // issue tile kt+1 into stage 1
                if (kt >= 1) { mb_wait(smem_u + MB_FREE1, pe1); pe1 ^= 1; }
                issue(kt + 1, 1);
                cpasync_arrive(smem_u + MB_FULL1);
            }
            mb_wait(smem_u + MB_FULL0, pf0); pf0 ^= 1;
            compute(0);
            mb_arrive(smem_u + MB_FREE0);
        }
        // ---- sub-iter s=1 (tile kt+1) ----
        if (kt + 1 < NKT) {
            if (kt + 2 < NKT) {                       // issue tile kt+2 into stage 0
                mb_wait(smem_u + MB_FREE0, pe0); pe0 ^= 1;
                issue(kt + 2, 0);
                cpasync_arrive(smem_u + MB_FULL0);
            }
            mb_wait(smem_u + MB_FULL1, pf1); pf1 ^= 1;
            compute(1);
            mb_arrive(smem_u + MB_FREE1);
        }
    }

    // ---- epilogue ----
    const int lrow = lane >> 2;
    const int lcol = (lane & 3) * 2;
#pragma unroll
    for (int mt = 0; mt < 2; mt++) {
#pragma unroll
        for (int nt = 0; nt < 8; nt++) {
            const int gr0 = row0 + warp_m + mt * 16 + lrow;
            const int gn  = col0 + warp_n + nt * 8 + lcol;
#pragma unroll
            for (int half = 0; half < 2; half++) {
                const int r = gr0 + half * 8;
                float v0 = acc[mt][nt][half * 2 + 0];
                float v1 = acc[mt][nt][half * 2 + 1];
                if (EPI) {
                    const int f = r & 31;
                    v0 = fmaxf(v0 + bias[f * 1024 + gn], 0.0f);
                    v1 = fmaxf(v1 + bias[f * 1024 + gn + 1], 0.0f);
                    *(float2*)(out + r * 1024 + gn) = make_float2(v0, v1);
                } else {
                    const int b = r >> 5, f = r & 31;
                    const int addr = (b * 32 + (gn >> 5)) * 1024 + f * 32 + (gn & 31);
                    *(float2*)(&Ad[addr]) = make_float2(to_tf32(v0), to_tf32(v1));
                }
            }
        }
    }
}

// ---------------- launch ----------------
extern "C" void kernel_launch(void* const* d_in, const int* in_sizes, int n_in,
                              void* d_out, int out_size) {
    const float* X     = (const float*)d_in[0];
    const float* nodes = (const float*)d_in[1];
    const float* bias  = (const float*)d_in[2];
    float* out = (float*)d_out;

    cudaFuncSetAttribute(entangler_mma<false>,
                         cudaFuncAttributeMaxDynamicSharedMemorySize, SMEM_BYTES);
    cudaFuncSetAttribute(entangler_mma<true>,
                         cudaFuncAttributeMaxDynamicSharedMemorySize, SMEM_BYTES);

    prep_x<<<MROWS, dim3(32, 32)>>>(X);
    prep_w<<<dim3(32, 32, NSTEPS), dim3(32, 32)>>>(nodes);

    dim3 grid(NCOLS / BN, MROWS / BM);   // (8, 64) = 512 CTAs
    entangler_mma<false><<<grid, NTHREADS, SMEM_BYTES>>>(0, 1, 0, bias, nullptr);
    entangler_mma<false><<<grid, NTHREADS, SMEM_BYTES>>>(1, 0, 1, bias, nullptr);
    entangler_mma<false><<<grid, NTHREADS, SMEM_BYTES>>>(0, 1, 2, bias, nullptr);
    entangler_mma<false><<<grid, NTHREADS, SMEM_BYTES>>>(1, 0, 3, bias, nullptr);
    entangler_mma<false><<<grid, NTHREADS, SMEM_BYTES>>>(0, 1, 4, bias, nullptr);
    entangler_mma<true ><<<grid, NTHREADS, SMEM_BYTES>>>(1, 0, 5, bias, out);
}